// round 1
// baseline (speedup 1.0000x reference)
#include <cuda_runtime.h>
#include <cuda_bf16.h>
#include <cstdint>

#define BB 64
#define NN 1024
#define CC 128
#define HH1 256
#define HH2 128
#define NW  32          // N/32 mask words per row
#define BN  (BB*NN)

// ---------------- scratch (device globals; no allocation allowed) ----------------
__device__ float    g_x0[(size_t)BB*NN*CC];   // 33.5 MB
__device__ float    g_x1[(size_t)BB*NN*CC];   // 33.5 MB
__device__ unsigned g_adj[(size_t)BB*NN*NW];  // 8 MB packed adjacency bits
__device__ float    g_sc[6*(size_t)BN];       // per-node: s, exp(s), exp(.2s), t, exp(t), exp(.2t)
__device__ float    g_pool[BB*CC];

// ---------------- kernel 1: x0 = node_features @ W_in ----------------
__global__ void k_xin(const float* __restrict__ nf, const float* __restrict__ Win) {
    int row = blockIdx.x;          // 0..BN-1
    int c   = threadIdx.x;         // 0..127
    float f0 = __ldg(nf + row*3 + 0);
    float f1 = __ldg(nf + row*3 + 1);
    float f2 = __ldg(nf + row*3 + 2);
    g_x0[(size_t)row*CC + c] = f0*__ldg(Win + c) + f1*__ldg(Win + CC + c) + f2*__ldg(Win + 2*CC + c);
}

// ---------------- kernel 2: pack adjacency to bits (warp ballot) ----------------
__global__ void k_pack(const int* __restrict__ adj) {
    size_t g = (size_t)blockIdx.x*blockDim.x + threadIdx.x;   // one element per thread
    unsigned bal = __ballot_sync(0xffffffffu, adj[g] > 0);
    if ((threadIdx.x & 31) == 0) g_adj[g >> 5] = bal;
}

// ---------------- kernel 3: per-node attention scalars ----------------
// s = x . a_src ; t = x . a_dst ; store s, e^s, e^{.2s}, t, e^t, e^{.2t}
__global__ void k_scalars(int dir, const float* __restrict__ asrc, const float* __restrict__ adst) {
    const float* x = dir ? g_x1 : g_x0;
    int warp = (blockIdx.x*blockDim.x + threadIdx.x) >> 5;
    int lane = threadIdx.x & 31;
    if (warp >= BN) return;
    float4 xv = ((const float4*)(x + (size_t)warp*CC))[lane];
    float4 av = __ldg(((const float4*)asrc) + lane);
    float4 dv = __ldg(((const float4*)adst) + lane);
    float s = xv.x*av.x + xv.y*av.y + xv.z*av.z + xv.w*av.w;
    float d = xv.x*dv.x + xv.y*dv.y + xv.z*dv.z + xv.w*dv.w;
    #pragma unroll
    for (int o = 16; o > 0; o >>= 1) {
        s += __shfl_down_sync(0xffffffffu, s, o);
        d += __shfl_down_sync(0xffffffffu, d, o);
    }
    if (lane == 0) {
        g_sc[0*(size_t)BN + warp] = s;
        g_sc[1*(size_t)BN + warp] = __expf(s);
        g_sc[2*(size_t)BN + warp] = __expf(0.2f*s);
        g_sc[3*(size_t)BN + warp] = d;
        g_sc[4*(size_t)BN + warp] = __expf(d);
        g_sc[5*(size_t)BN + warp] = __expf(0.2f*d);
    }
}

// ---------------- kernel 4: fused masked-softmax aggregation + relu ----------------
// out[b,i,:] = relu( (sum_j p_ij x[b,j,:]) / (sum_j p_ij) )
// p_ij = mask_ij * ( (s_i+t_j>0) ? e^{s_i} e^{t_j} : e^{.2 s_i} e^{.2 t_j} )
__global__ __launch_bounds__(256) void k_gat(int dir) {
    __shared__ float    sx[32][128];     // x tile [j][c]
    __shared__ float    sp[32][36];      // pT[j][i] (padded for alignment/conflicts)
    __shared__ float    sjs[3][32];      // t_j, e^t, e^{.2t}
    __shared__ float    ssi[3][32];      // s_i, e^s, e^{.2s}
    __shared__ unsigned smask[32];
    __shared__ float    srp[32][9];      // rowsum partials
    __shared__ float    sinv[32];

    const float* __restrict__ x = dir ? g_x1 : g_x0;
    float* __restrict__ xout    = dir ? g_x0 : g_x1;

    const int b  = blockIdx.y;
    const int i0 = blockIdx.x * 32;
    const int t  = threadIdx.x;
    const float* xb = x + (size_t)b*NN*CC;

    if (t < 32) {
        int node = b*NN + i0 + t;
        ssi[0][t] = g_sc[node];
        ssi[1][t] = g_sc[(size_t)BN + node];
        ssi[2][t] = g_sc[2*(size_t)BN + node];
    }

    const int iq = t >> 5, cq = t & 31;    // ffma tiling: rows iq*4.., cols cq*4..
    const int pi = t & 31, pjq = t >> 5;   // p-gen tiling: i=pi, j in pjq*4..

    float acc[4][4];
    #pragma unroll
    for (int a = 0; a < 4; a++)
        #pragma unroll
        for (int c = 0; c < 4; c++) acc[a][c] = 0.f;
    float rsum = 0.f;

    for (int jt = 0; jt < 32; ++jt) {
        __syncthreads();
        // stage x tile (32x128 f32 = 1024 float4)
        {
            const float4* src = (const float4*)(xb + (size_t)jt*32*CC);
            float4* dst = (float4*)&sx[0][0];
            #pragma unroll
            for (int k = 0; k < 4; k++) dst[t + 256*k] = src[t + 256*k];
        }
        if (t < 32) {
            int node = b*NN + jt*32 + t;
            sjs[0][t] = g_sc[3*(size_t)BN + node];
            sjs[1][t] = g_sc[4*(size_t)BN + node];
            sjs[2][t] = g_sc[5*(size_t)BN + node];
        } else if (t >= 64 && t < 96) {
            int ii = t - 64;
            smask[ii] = g_adj[((size_t)(b*NN + i0 + ii))*NW + jt];
        }
        __syncthreads();
        // compute P tile (each thread: fixed i, 4 j's)
        {
            const float si = ssi[0][pi], Ei = ssi[1][pi], Esi = ssi[2][pi];
            const unsigned m = smask[pi];
            #pragma unroll
            for (int k = 0; k < 4; k++) {
                int j = pjq*4 + k;
                float tj = sjs[0][j];
                float p = (si + tj > 0.f) ? (Ei * sjs[1][j]) : (Esi * sjs[2][j]);
                if (!((m >> j) & 1u)) p = 0.f;
                sp[j][pi] = p;
                rsum += p;
            }
        }
        __syncthreads();
        // FFMA: acc[ii][cc] += P[j][iq*4+ii] * x[j][cq*4+cc]
        #pragma unroll 8
        for (int j = 0; j < 32; ++j) {
            float4 pv = *(const float4*)&sp[j][iq*4];
            float4 xv = *(const float4*)&sx[j][cq*4];
            acc[0][0] += pv.x*xv.x; acc[0][1] += pv.x*xv.y; acc[0][2] += pv.x*xv.z; acc[0][3] += pv.x*xv.w;
            acc[1][0] += pv.y*xv.x; acc[1][1] += pv.y*xv.y; acc[1][2] += pv.y*xv.z; acc[1][3] += pv.y*xv.w;
            acc[2][0] += pv.z*xv.x; acc[2][1] += pv.z*xv.y; acc[2][2] += pv.z*xv.z; acc[2][3] += pv.z*xv.w;
            acc[3][0] += pv.w*xv.x; acc[3][1] += pv.w*xv.y; acc[3][2] += pv.w*xv.z; acc[3][3] += pv.w*xv.w;
        }
    }

    // rowsum reduce (8 partials per i)
    srp[pi][pjq] = rsum;
    __syncthreads();
    if (t < 32) {
        float s = 0.f;
        #pragma unroll
        for (int q = 0; q < 8; q++) s += srp[t][q];
        sinv[t] = 1.f / s;
    }
    __syncthreads();
    // writeback: relu(acc * inv)
    #pragma unroll
    for (int a = 0; a < 4; a++) {
        int i = iq*4 + a;
        float inv = sinv[i];
        float4 o;
        o.x = fmaxf(acc[a][0]*inv, 0.f);
        o.y = fmaxf(acc[a][1]*inv, 0.f);
        o.z = fmaxf(acc[a][2]*inv, 0.f);
        o.w = fmaxf(acc[a][3]*inv, 0.f);
        *(float4*)(xout + ((size_t)b*NN + i0 + i)*CC + cq*4) = o;
    }
}

// ---------------- kernel 5: mean pool over N ----------------
__global__ void k_pool() {
    const int b = blockIdx.x;
    const int t = threadIdx.x;          // 512 threads: 4 n-chunks x 128 c
    const int c  = t & 127;
    const int nq = t >> 7;              // 0..3
    __shared__ float part[4][128];
    const float* xb = g_x0 + (size_t)b*NN*CC;   // layer-2 output lives in g_x0
    float s = 0.f;
    for (int n = nq; n < NN; n += 4) s += xb[(size_t)n*CC + c];
    part[nq][c] = s;
    __syncthreads();
    if (t < 128) g_pool[b*CC + t] = (part[0][t] + part[1][t] + part[2][t] + part[3][t]) * (1.0f/NN);
}

// ---------------- kernel 6: MLP head + softmax + value ----------------
__global__ __launch_bounds__(256) void k_head(
    const float* __restrict__ W1, const float* __restrict__ b1,
    const float* __restrict__ W2, const float* __restrict__ b2,
    const float* __restrict__ Wpi, const float* __restrict__ bpi,
    const float* __restrict__ Wv, const float* __restrict__ bv,
    float* __restrict__ out)
{
    const int b = blockIdx.x, t = threadIdx.x;
    __shared__ float sp_[128];
    __shared__ float sh1[256];
    __shared__ float sh2[128];
    __shared__ float red[256];
    if (t < 128) sp_[t] = g_pool[b*CC + t];
    __syncthreads();
    // h1 = relu(pool @ W1 + b1), W1 [128,256]
    {
        float s = __ldg(b1 + t);
        #pragma unroll 8
        for (int k = 0; k < 128; k++) s += sp_[k] * __ldg(W1 + k*HH1 + t);
        sh1[t] = fmaxf(s, 0.f);
    }
    __syncthreads();
    // h2 = relu(h1 @ W2 + b2), W2 [256,128]
    if (t < 128) {
        float s = __ldg(b2 + t);
        #pragma unroll 8
        for (int k = 0; k < 256; k++) s += sh1[k] * __ldg(W2 + k*HH2 + t);
        sh2[t] = fmaxf(s, 0.f);
    }
    __syncthreads();
    // logits = h2 @ Wpi + bpi, [1024]; 4 columns per thread
    float lg[4];
    float lmax = -1e30f;
    #pragma unroll
    for (int m = 0; m < 4; m++) {
        int col = t + 256*m;
        float s = __ldg(bpi + col);
        #pragma unroll 8
        for (int k = 0; k < 128; k++) s += sh2[k] * __ldg(Wpi + k*NN + col);
        lg[m] = s;
        lmax = fmaxf(lmax, s);
    }
    red[t] = lmax; __syncthreads();
    for (int s2 = 128; s2 > 0; s2 >>= 1) { if (t < s2) red[t] = fmaxf(red[t], red[t+s2]); __syncthreads(); }
    float mx = red[0];
    __syncthreads();
    float lsum = 0.f;
    #pragma unroll
    for (int m = 0; m < 4; m++) { lg[m] = __expf(lg[m] - mx); lsum += lg[m]; }
    red[t] = lsum; __syncthreads();
    for (int s2 = 128; s2 > 0; s2 >>= 1) { if (t < s2) red[t] += red[t+s2]; __syncthreads(); }
    float inv = 1.f / red[0];
    #pragma unroll
    for (int m = 0; m < 4; m++) out[(size_t)b*NN + t + 256*m] = lg[m]*inv;
    if (t == 0) {
        float s = __ldg(bv);
        for (int k = 0; k < 128; k++) s += sh2[k] * __ldg(Wv + k);
        out[(size_t)BB*NN + b] = s;
    }
}

// ---------------- launch ----------------
extern "C" void kernel_launch(void* const* d_in, const int* in_sizes, int n_in,
                              void* d_out, int out_size) {
    const float* nf    = (const float*)d_in[0];
    const int*   adj   = (const int*)  d_in[1];
    const float* Win   = (const float*)d_in[2];
    const float* asrc  = (const float*)d_in[3];
    const float* adst  = (const float*)d_in[4];
    const float* asrc2 = (const float*)d_in[5];
    const float* adst2 = (const float*)d_in[6];
    const float* W1    = (const float*)d_in[7];
    const float* b1    = (const float*)d_in[8];
    const float* W2    = (const float*)d_in[9];
    const float* b2    = (const float*)d_in[10];
    const float* Wpi   = (const float*)d_in[11];
    const float* bpi   = (const float*)d_in[12];
    const float* Wv    = (const float*)d_in[13];
    const float* bv    = (const float*)d_in[14];
    float* out = (float*)d_out;

    k_xin<<<BN, 128>>>(nf, Win);
    k_pack<<<(unsigned)(((size_t)BB*NN*NN)/256), 256>>>(adj);

    // layer 1: g_x0 -> g_x1
    k_scalars<<<BN/8, 256>>>(0, asrc, adst);
    k_gat<<<dim3(NN/32, BB), 256>>>(0);

    // layer 2: g_x1 -> g_x0
    k_scalars<<<BN/8, 256>>>(1, asrc2, adst2);
    k_gat<<<dim3(NN/32, BB), 256>>>(1);

    k_pool<<<BB, 512>>>();
    k_head<<<BB, 256>>>(W1, b1, W2, b2, Wpi, bpi, Wv, bv, out);
}